// round 1
// baseline (speedup 1.0000x reference)
#include <cuda_runtime.h>

#define NB   32        // batch
#define NE   200000    // entities
#define NT   1000000   // triples
#define NR   256       // relations
#define DQ   768       // question dim
#define DIN  1280      // DQ + 2*NR
#define NEB  (NE * NB) // 6.4M floats

// ---- device scratch (static; no allocation) ----
__device__ float g_x0T[NEB];          // transposed seed x: [e][b]
__device__ float g_xh[3 * NEB];       // hop outputs, entity-major
__device__ float g_hqT[DQ * NB];      // transposed h_q: [d][b]
__device__ float g_rT[3 * NR * NB];   // r per hop: [j][b]
__device__ float g_c[3 * NB];         // attention logits per hop

// ---- transpose (B x cols) -> (cols x B), mode selects destination ----
__global__ void k_transpose(const float* __restrict__ src, int cols, int mode) {
    __shared__ float s[32][33];
    float* dst = mode ? g_hqT : g_x0T;
    int lane = threadIdx.x, ty = threadIdx.y;
    int cbase = blockIdx.x * 32;
#pragma unroll
    for (int row = ty; row < 32; row += 8)              // row = b
        s[row][lane] = src[(size_t)row * cols + cbase + lane];
    __syncthreads();
#pragma unroll
    for (int row = ty; row < 32; row += 8)              // row = col offset
        dst[(size_t)(cbase + row) * NB + lane] = s[lane][row];
}

__global__ void k_zero() {
    int i = blockIdx.x * blockDim.x + threadIdx.x;
    if (i < 3 * NEB / 4)
        reinterpret_cast<float4*>(g_xh)[i] = make_float4(0.f, 0.f, 0.f, 0.f);
}

// ---- tiny dense layer: r = concat @ W_inf.T ; c = concat @ W_att.T ----
// concat[b] = [h_q[b], r_{hop-1}[b], r_{hop-2}[b], pad]; zero pad is skipped.
// thread (lane=b, ty): j = blockIdx.x*8 + ty; blockIdx.x==32 -> W_att row.
__global__ void k_gemm(const float* __restrict__ W_inf,
                       const float* __restrict__ W_att, int hop) {
    int lane = threadIdx.x;
    int j = blockIdx.x * 8 + threadIdx.y;
    const float* w;
    bool is_att = (blockIdx.x == 32);
    if (is_att) {
        if (threadIdx.y != 0) return;
        w = W_att;
    } else {
        w = W_inf + (size_t)j * DIN;
    }
    float a0 = 0.f, a1 = 0.f, a2 = 0.f, a3 = 0.f;
#pragma unroll 4
    for (int d = 0; d < DQ; d += 4) {
        a0 += g_hqT[(d + 0) * NB + lane] * w[d + 0];
        a1 += g_hqT[(d + 1) * NB + lane] * w[d + 1];
        a2 += g_hqT[(d + 2) * NB + lane] * w[d + 2];
        a3 += g_hqT[(d + 3) * NB + lane] * w[d + 3];
    }
    if (hop >= 1) {   // most recent relation first
        const float* r1 = g_rT + (hop - 1) * NR * NB;
        const float* wd = w + DQ;
#pragma unroll 4
        for (int k = 0; k < NR; k += 4) {
            a0 += r1[(k + 0) * NB + lane] * wd[k + 0];
            a1 += r1[(k + 1) * NB + lane] * wd[k + 1];
            a2 += r1[(k + 2) * NB + lane] * wd[k + 2];
            a3 += r1[(k + 3) * NB + lane] * wd[k + 3];
        }
    }
    if (hop >= 2) {
        const float* r2 = g_rT + (hop - 2) * NR * NB;
        const float* wd = w + DQ + NR;
#pragma unroll 4
        for (int k = 0; k < NR; k += 4) {
            a0 += r2[(k + 0) * NB + lane] * wd[k + 0];
            a1 += r2[(k + 1) * NB + lane] * wd[k + 1];
            a2 += r2[(k + 2) * NB + lane] * wd[k + 2];
            a3 += r2[(k + 3) * NB + lane] * wd[k + 3];
        }
    }
    float acc = (a0 + a1) + (a2 + a3);
    if (is_att) g_c[hop * NB + lane] = acc;
    else        g_rT[hop * NR * NB + j * NB + lane] = acc;
}

// ---- gather * relation -> scatter-add. One warp = 32 triples; lane = b. ----
__global__ void k_scatter(const int* __restrict__ subj,
                          const int* __restrict__ rel,
                          const int* __restrict__ obj, int hop) {
    __shared__ float s_r[NR * NB];   // 32 KB relation table [r][b]
    const float* rT = g_rT + hop * NR * NB;
    for (int i = threadIdx.x; i < NR * NB; i += blockDim.x) s_r[i] = rT[i];
    __syncthreads();

    const float* __restrict__ xin = (hop == 0) ? g_x0T : (g_xh + (hop - 1) * NEB);
    float* xout = g_xh + hop * NEB;

    int lane = threadIdx.x & 31;
    int warp = (blockIdx.x * blockDim.x + threadIdx.x) >> 5;
    int t0 = warp << 5;
    if (t0 >= NT) return;

    int s_i = subj[t0 + lane];
    int r_i = rel[t0 + lane];
    int o_i = obj[t0 + lane];

#pragma unroll 1
    for (int i = 0; i < 32; i++) {
        int s = __shfl_sync(0xffffffffu, s_i, i);
        float xv = xin[s * NB + lane];                 // one 128B line
        if (__ballot_sync(0xffffffffu, xv != 0.0f)) {  // exploit sparsity
            int r = __shfl_sync(0xffffffffu, r_i, i);
            int o = __shfl_sync(0xffffffffu, o_i, i);
            float p = xv * s_r[r * NB + lane];
            if (p != 0.0f) atomicAdd(&xout[o * NB + lane], p);
        }
    }
}

// ---- softmax over hop logits + weighted combine, transpose back to (B,NE) ----
__global__ void k_combine(float* __restrict__ out) {
    __shared__ float s[32][33];
    int lane = threadIdx.x, ty = threadIdx.y;
    float c0 = g_c[lane], c1 = g_c[NB + lane], c2 = g_c[2 * NB + lane];
    float m = fmaxf(c0, fmaxf(c1, c2));
    float e0 = expf(c0 - m), e1 = expf(c1 - m), e2 = expf(c2 - m);
    float inv = 1.0f / (e0 + e1 + e2);
    float a0 = e0 * inv, a1 = e1 * inv, a2 = e2 * inv;

    int ebase = blockIdx.x * 32;
#pragma unroll
    for (int row = ty; row < 32; row += 8) {           // row = e offset, lane = b
        int idx = (ebase + row) * NB + lane;
        s[row][lane] = a0 * g_xh[idx] + a1 * g_xh[NEB + idx] + a2 * g_xh[2 * NEB + idx];
    }
    __syncthreads();
#pragma unroll
    for (int row = ty; row < 32; row += 8)             // row = b, lane = e offset
        out[(size_t)row * NE + ebase + lane] = s[lane][row];
}

extern "C" void kernel_launch(void* const* d_in, const int* in_sizes, int n_in,
                              void* d_out, int out_size) {
    const float* x     = (const float*)d_in[0];
    const float* h_q   = (const float*)d_in[1];
    const float* W_inf = (const float*)d_in[2];
    const float* W_att = (const float*)d_in[3];
    const int*   subj  = (const int*)d_in[4];
    const int*   rel   = (const int*)d_in[5];
    const int*   obj   = (const int*)d_in[6];
    float* out = (float*)d_out;

    dim3 tb(32, 8);
    k_transpose<<<NE / 32, tb>>>(x, NE, 0);
    k_transpose<<<DQ / 32, tb>>>(h_q, DQ, 1);
    k_zero<<<(3 * NEB / 4 + 255) / 256, 256>>>();

    int nwarps = NT / 32;                // 31250
    int sblocks = (nwarps + 7) / 8;      // 3907 blocks of 8 warps
    for (int hop = 0; hop < 3; hop++) {
        k_gemm<<<33, tb>>>(W_inf, W_att, hop);
        k_scatter<<<sblocks, 256>>>(subj, rel, obj, hop);
    }
    k_combine<<<NE / 32, tb>>>(out);
}

// round 2
// speedup vs baseline: 1.7611x; 1.7611x over previous
#include <cuda_runtime.h>

#define NB   32        // batch
#define NE   200000    // entities
#define NT   1000000   // triples
#define NR   256       // relations
#define DQ   768       // question dim
#define DIN  1280      // DQ + 2*NR
#define NEB  (NE * NB) // 6.4M floats
#define NJ   257       // 256 W_inf rows + 1 W_att row

// ---- device scratch (static; no allocation) ----
__device__ float g_x0T[NEB];          // transposed seed x: [e][b]
__device__ float g_xh[3 * NEB];       // hop outputs, entity-major
__device__ float g_hqT[DQ * NB];      // transposed h_q: [d][b]
__device__ float g_rT[3 * NR * NB];   // r per hop: [j][b]
__device__ float g_c[3 * NB];         // attention logits per hop
__device__ float g_base[NJ * NB];     // hop-invariant h_q part of every output

// ---- transpose (B x cols) -> (cols x B), mode selects destination ----
__global__ void k_transpose(const float* __restrict__ src, int cols, int mode) {
    __shared__ float s[32][33];
    float* dst = mode ? g_hqT : g_x0T;
    int lane = threadIdx.x, ty = threadIdx.y;
    int cbase = blockIdx.x * 32;
#pragma unroll
    for (int row = ty; row < 32; row += 8)              // row = b
        s[row][lane] = src[(size_t)row * cols + cbase + lane];
    __syncthreads();
#pragma unroll
    for (int row = ty; row < 32; row += 8)              // row = col offset
        dst[(size_t)(cbase + row) * NB + lane] = s[lane][row];
}

__global__ void k_zero() {
    int i = blockIdx.x * blockDim.x + threadIdx.x;
    if (i < 3 * NEB / 4)
        reinterpret_cast<float4*>(g_xh)[i] = make_float4(0.f, 0.f, 0.f, 0.f);
}

// ---- base = h_q @ [W_inf; W_att][:, :768].T  (hop-invariant; == hop-0 output)
// One block per output row j. 8 d-slices of 96, shared reduce.
__global__ void k_gemm_base(const float* __restrict__ W_inf,
                            const float* __restrict__ W_att) {
    int lane = threadIdx.x, ty = threadIdx.y;
    int j = blockIdx.x;
    const float* w = (j == 256) ? W_att : W_inf + (size_t)j * DIN;
    float a0 = 0.f, a1 = 0.f, a2 = 0.f, a3 = 0.f;
    int d0 = ty * 96;
#pragma unroll 6
    for (int d = d0; d < d0 + 96; d += 4) {
        a0 += g_hqT[(d + 0) * NB + lane] * w[d + 0];
        a1 += g_hqT[(d + 1) * NB + lane] * w[d + 1];
        a2 += g_hqT[(d + 2) * NB + lane] * w[d + 2];
        a3 += g_hqT[(d + 3) * NB + lane] * w[d + 3];
    }
    __shared__ float s[8][32];
    s[ty][lane] = (a0 + a1) + (a2 + a3);
    __syncthreads();
    if (ty == 0) {
        float t = 0.f;
#pragma unroll
        for (int k = 0; k < 8; k++) t += s[k][lane];
        g_base[j * NB + lane] = t;
        if (j == 256) g_c[lane] = t;            // c_0
        else          g_rT[j * NB + lane] = t;  // r_0
    }
}

// ---- hop 1/2 increment: out = base + r_parts @ W[:, 768:768+hop*256].T ----
__global__ void k_gemm_hop(const float* __restrict__ W_inf,
                           const float* __restrict__ W_att, int hop) {
    int lane = threadIdx.x, ty = threadIdx.y;
    int j = blockIdx.x;
    const float* w = (j == 256) ? W_att : W_inf + (size_t)j * DIN;
    float acc = 0.f;
    // segment 0: most recent relation r_{hop-1}, weights w[768 .. 768+256)
    {
        const float* r1 = g_rT + (hop - 1) * NR * NB;
        const float* wd = w + DQ;
        int k0 = ty * 32;
#pragma unroll 8
        for (int k = k0; k < k0 + 32; k++)
            acc += r1[k * NB + lane] * wd[k];
    }
    if (hop == 2) {   // segment 1: r_{hop-2}, weights w[768+256 .. 768+512)
        const float* r2 = g_rT;                 // hop-0 r
        const float* wd = w + DQ + NR;
        int k0 = ty * 32;
#pragma unroll 8
        for (int k = k0; k < k0 + 32; k++)
            acc += r2[k * NB + lane] * wd[k];
    }
    __shared__ float s[8][32];
    s[ty][lane] = acc;
    __syncthreads();
    if (ty == 0) {
        float t = g_base[j * NB + lane];
#pragma unroll
        for (int k = 0; k < 8; k++) t += s[k][lane];
        if (j == 256) g_c[hop * NB + lane] = t;
        else          g_rT[hop * NR * NB + j * NB + lane] = t;
    }
}

// ---- gather * relation -> scatter-add. One warp = 32 triples; lane = b. ----
// Relation table read directly from global (32KB, L1/L2-resident; only
// active triples touch it).
__global__ void k_scatter(const int* __restrict__ subj,
                          const int* __restrict__ rel,
                          const int* __restrict__ obj, int hop) {
    const float* __restrict__ rT = g_rT + hop * NR * NB;
    const float* __restrict__ xin = (hop == 0) ? g_x0T : (g_xh + (hop - 1) * NEB);
    float* xout = g_xh + hop * NEB;

    int lane = threadIdx.x & 31;
    int warp = (blockIdx.x * blockDim.x + threadIdx.x) >> 5;
    int t0 = warp << 5;
    if (t0 >= NT) return;

    int s_i = subj[t0 + lane];
    int r_i = rel[t0 + lane];
    int o_i = obj[t0 + lane];

#pragma unroll 1
    for (int i = 0; i < 32; i++) {
        int s = __shfl_sync(0xffffffffu, s_i, i);
        float xv = xin[s * NB + lane];                 // one 128B line
        if (__ballot_sync(0xffffffffu, xv != 0.0f)) {  // exploit sparsity
            int r = __shfl_sync(0xffffffffu, r_i, i);
            int o = __shfl_sync(0xffffffffu, o_i, i);
            float p = xv * rT[r * NB + lane];
            if (p != 0.0f) atomicAdd(&xout[o * NB + lane], p);
        }
    }
}

// ---- softmax over hop logits + weighted combine, transpose back to (B,NE) ----
__global__ void k_combine(float* __restrict__ out) {
    __shared__ float s[32][33];
    int lane = threadIdx.x, ty = threadIdx.y;
    float c0 = g_c[lane], c1 = g_c[NB + lane], c2 = g_c[2 * NB + lane];
    float m = fmaxf(c0, fmaxf(c1, c2));
    float e0 = expf(c0 - m), e1 = expf(c1 - m), e2 = expf(c2 - m);
    float inv = 1.0f / (e0 + e1 + e2);
    float a0 = e0 * inv, a1 = e1 * inv, a2 = e2 * inv;

    int ebase = blockIdx.x * 32;
#pragma unroll
    for (int row = ty; row < 32; row += 8) {           // row = e offset, lane = b
        int idx = (ebase + row) * NB + lane;
        s[row][lane] = a0 * g_xh[idx] + a1 * g_xh[NEB + idx] + a2 * g_xh[2 * NEB + idx];
    }
    __syncthreads();
#pragma unroll
    for (int row = ty; row < 32; row += 8)             // row = b, lane = e offset
        out[(size_t)row * NE + ebase + lane] = s[lane][row];
}

extern "C" void kernel_launch(void* const* d_in, const int* in_sizes, int n_in,
                              void* d_out, int out_size) {
    const float* x     = (const float*)d_in[0];
    const float* h_q   = (const float*)d_in[1];
    const float* W_inf = (const float*)d_in[2];
    const float* W_att = (const float*)d_in[3];
    const int*   subj  = (const int*)d_in[4];
    const int*   rel   = (const int*)d_in[5];
    const int*   obj   = (const int*)d_in[6];
    float* out = (float*)d_out;

    dim3 tb(32, 8);
    k_transpose<<<NE / 32, tb>>>(x, NE, 0);
    k_transpose<<<DQ / 32, tb>>>(h_q, DQ, 1);
    k_zero<<<(3 * NEB / 4 + 255) / 256, 256>>>();

    int nwarps = NT / 32;                // 31250
    int sblocks = (nwarps + 7) / 8;      // 3907 blocks of 8 warps

    k_gemm_base<<<NJ, tb>>>(W_inf, W_att);   // r_0, c_0, base
    k_scatter<<<sblocks, 256>>>(subj, rel, obj, 0);
    for (int hop = 1; hop < 3; hop++) {
        k_gemm_hop<<<NJ, tb>>>(W_inf, W_att, hop);
        k_scatter<<<sblocks, 256>>>(subj, rel, obj, hop);
    }
    k_combine<<<NE / 32, tb>>>(out);
}

// round 3
// speedup vs baseline: 2.4737x; 1.4046x over previous
#include <cuda_runtime.h>

#define NB   32        // batch
#define NE   200000    // entities
#define NT   1000000   // triples
#define NR   256       // relations
#define DQ   768       // question dim
#define DIN  1280      // DQ + 2*NR
#define NEB  (NE * NB) // 6.4M floats
#define NJ   257       // 256 W_inf rows + 1 W_att row
#define NW   (NE / 32) // 6250 mask words per hop

// ---- device scratch (static; no allocation) ----
__device__ float g_x0T[NEB];           // transposed seed x: [e][b]
__device__ float g_xh[3 * NEB];        // hop outputs, entity-major
__device__ float g_hqT[DQ * NB];       // transposed h_q: [d][b]
__device__ float g_rT[3 * NR * NB];    // r per hop: [j][b]
__device__ float g_c[3 * NB];          // attention logits per hop
__device__ float g_base[NJ * NB];      // hop-invariant h_q part
__device__ unsigned g_mask[4 * NW];    // active-entity bitmask per hop input

// ---- transpose x (B x NE) -> (NE x B) and build hop-0 activity mask ----
__global__ void k_transpose_x(const float* __restrict__ src) {
    __shared__ float s[32][33];
    __shared__ unsigned smask;
    int lane = threadIdx.x, ty = threadIdx.y;
    if (ty == 0 && lane == 0) smask = 0;
    int cbase = blockIdx.x * 32;
#pragma unroll
    for (int row = ty; row < 32; row += 8)              // row = b
        s[row][lane] = src[(size_t)row * NE + cbase + lane];
    __syncthreads();
    unsigned local = 0;
#pragma unroll
    for (int row = ty; row < 32; row += 8) {            // row = entity offset
        float v = s[lane][row];                         // lane = b
        g_x0T[(size_t)(cbase + row) * NB + lane] = v;
        unsigned b = __ballot_sync(0xffffffffu, v != 0.0f);
        if (lane == 0 && b) local |= 1u << row;
    }
    if (lane == 0 && local) atomicOr(&smask, local);
    __syncthreads();
    if (ty == 0 && lane == 0) g_mask[blockIdx.x] = smask;
}

// ---- transpose h_q (B x DQ) -> (DQ x B) ----
__global__ void k_transpose_hq(const float* __restrict__ src) {
    __shared__ float s[32][33];
    int lane = threadIdx.x, ty = threadIdx.y;
    int cbase = blockIdx.x * 32;
#pragma unroll
    for (int row = ty; row < 32; row += 8)
        s[row][lane] = src[(size_t)row * DQ + cbase + lane];
    __syncthreads();
#pragma unroll
    for (int row = ty; row < 32; row += 8)
        g_hqT[(cbase + row) * NB + lane] = s[lane][row];
}

// ---- zero hop outputs + masks 1..3 ----
__global__ void k_zero() {
    int i = blockIdx.x * blockDim.x + threadIdx.x;
    const int nf4 = 3 * NEB / 4;
    if (i < nf4) {
        reinterpret_cast<float4*>(g_xh)[i] = make_float4(0.f, 0.f, 0.f, 0.f);
    } else {
        int j = i - nf4;
        if (j < 3 * NW) g_mask[NW + j] = 0u;
    }
}

// ---- base = h_q @ [W_inf; W_att][:, :768].T  (hop-invariant; == hop-0 output)
__global__ void k_gemm_base(const float* __restrict__ W_inf,
                            const float* __restrict__ W_att) {
    int lane = threadIdx.x, ty = threadIdx.y;
    int j = blockIdx.x;
    const float* w = (j == 256) ? W_att : W_inf + (size_t)j * DIN;
    float a0 = 0.f, a1 = 0.f, a2 = 0.f, a3 = 0.f;
    int d0 = ty * 96;
#pragma unroll 6
    for (int d = d0; d < d0 + 96; d += 4) {
        a0 += g_hqT[(d + 0) * NB + lane] * w[d + 0];
        a1 += g_hqT[(d + 1) * NB + lane] * w[d + 1];
        a2 += g_hqT[(d + 2) * NB + lane] * w[d + 2];
        a3 += g_hqT[(d + 3) * NB + lane] * w[d + 3];
    }
    __shared__ float s[8][32];
    s[ty][lane] = (a0 + a1) + (a2 + a3);
    __syncthreads();
    if (ty == 0) {
        float t = 0.f;
#pragma unroll
        for (int k = 0; k < 8; k++) t += s[k][lane];
        g_base[j * NB + lane] = t;
        if (j == 256) g_c[lane] = t;            // c_0
        else          g_rT[j * NB + lane] = t;  // r_0
    }
}

// ---- hop 1/2 increment: out = base + r_parts @ W[:, 768:768+hop*256].T ----
__global__ void k_gemm_hop(const float* __restrict__ W_inf,
                           const float* __restrict__ W_att, int hop) {
    int lane = threadIdx.x, ty = threadIdx.y;
    int j = blockIdx.x;
    const float* w = (j == 256) ? W_att : W_inf + (size_t)j * DIN;
    float acc = 0.f;
    {   // most recent relation r_{hop-1}, weights w[768 .. 1024)
        const float* r1 = g_rT + (hop - 1) * NR * NB;
        const float* wd = w + DQ;
        int k0 = ty * 32;
#pragma unroll 8
        for (int k = k0; k < k0 + 32; k++)
            acc += r1[k * NB + lane] * wd[k];
    }
    if (hop == 2) {   // r_0, weights w[1024 .. 1280)
        const float* r2 = g_rT;
        const float* wd = w + DQ + NR;
        int k0 = ty * 32;
#pragma unroll 8
        for (int k = k0; k < k0 + 32; k++)
            acc += r2[k * NB + lane] * wd[k];
    }
    __shared__ float s[8][32];
    s[ty][lane] = acc;
    __syncthreads();
    if (ty == 0) {
        float t = g_base[j * NB + lane];
#pragma unroll
        for (int k = 0; k < 8; k++) t += s[k][lane];
        if (j == 256) g_c[hop * NB + lane] = t;
        else          g_rT[hop * NR * NB + j * NB + lane] = t;
    }
}

// ---- masked gather * relation -> scatter-add. Thread = triple; work only
// on triples whose subject is active (bitmask), iterated via warp ballot. ----
__global__ void k_scatter(const int* __restrict__ subj,
                          const int* __restrict__ rel,
                          const int* __restrict__ obj, int hop) {
    const float* __restrict__ rT = g_rT + hop * NR * NB;
    const float* __restrict__ xin = (hop == 0) ? g_x0T : (g_xh + (hop - 1) * NEB);
    float* xout = g_xh + hop * NEB;
    const unsigned* __restrict__ min_ = g_mask + hop * NW;
    unsigned* mout = g_mask + (hop + 1) * NW;

    int lane = threadIdx.x & 31;
    int t = blockIdx.x * blockDim.x + threadIdx.x;

    int s_i = 0, r_i = 0, o_i = 0;
    bool act = false;
    if (t < NT) {
        s_i = subj[t];
        act = (min_[s_i >> 5] >> (s_i & 31)) & 1u;
        if (act) { r_i = rel[t]; o_i = obj[t]; }
    }
    unsigned bal = __ballot_sync(0xffffffffu, act);
    while (bal) {
        int i = __ffs(bal) - 1;
        bal &= bal - 1;
        int s = __shfl_sync(0xffffffffu, s_i, i);
        int r = __shfl_sync(0xffffffffu, r_i, i);
        int o = __shfl_sync(0xffffffffu, o_i, i);
        float p = xin[s * NB + lane] * rT[r * NB + lane];  // two 128B lines
        bool nz = (p != 0.0f);
        unsigned pb = __ballot_sync(0xffffffffu, nz);
        if (nz) atomicAdd(&xout[o * NB + lane], p);
        if (pb && lane == (__ffs(pb) - 1))
            atomicOr(&mout[o >> 5], 1u << (o & 31));
    }
}

// ---- softmax over hop logits + weighted combine, transpose back to (B,NE) ----
__global__ void k_combine(float* __restrict__ out) {
    __shared__ float s[32][33];
    int lane = threadIdx.x, ty = threadIdx.y;
    float c0 = g_c[lane], c1 = g_c[NB + lane], c2 = g_c[2 * NB + lane];
    float m = fmaxf(c0, fmaxf(c1, c2));
    float e0 = expf(c0 - m), e1 = expf(c1 - m), e2 = expf(c2 - m);
    float inv = 1.0f / (e0 + e1 + e2);
    float a0 = e0 * inv, a1 = e1 * inv, a2 = e2 * inv;

    int ebase = blockIdx.x * 32;
#pragma unroll
    for (int row = ty; row < 32; row += 8) {           // row = e offset, lane = b
        int idx = (ebase + row) * NB + lane;
        s[row][lane] = a0 * g_xh[idx] + a1 * g_xh[NEB + idx] + a2 * g_xh[2 * NEB + idx];
    }
    __syncthreads();
#pragma unroll
    for (int row = ty; row < 32; row += 8)             // row = b, lane = e offset
        out[(size_t)row * NE + ebase + lane] = s[lane][row];
}

extern "C" void kernel_launch(void* const* d_in, const int* in_sizes, int n_in,
                              void* d_out, int out_size) {
    const float* x     = (const float*)d_in[0];
    const float* h_q   = (const float*)d_in[1];
    const float* W_inf = (const float*)d_in[2];
    const float* W_att = (const float*)d_in[3];
    const int*   subj  = (const int*)d_in[4];
    const int*   rel   = (const int*)d_in[5];
    const int*   obj   = (const int*)d_in[6];
    float* out = (float*)d_out;

    dim3 tb(32, 8);
    k_transpose_x<<<NE / 32, tb>>>(x);
    k_transpose_hq<<<DQ / 32, tb>>>(h_q);
    int zthreads = 3 * NEB / 4 + 3 * NW;
    k_zero<<<(zthreads + 255) / 256, 256>>>();

    int sblocks = (NT + 255) / 256;

    k_gemm_base<<<NJ, tb>>>(W_inf, W_att);   // r_0, c_0, base
    k_scatter<<<sblocks, 256>>>(subj, rel, obj, 0);
    for (int hop = 1; hop < 3; hop++) {
        k_gemm_hop<<<NJ, tb>>>(W_inf, W_att, hop);
        k_scatter<<<sblocks, 256>>>(subj, rel, obj, hop);
    }
    k_combine<<<NE / 32, tb>>>(out);
}

// round 4
// speedup vs baseline: 3.7475x; 1.5150x over previous
#include <cuda_runtime.h>

#define NB   32        // batch
#define NE   200000    // entities
#define NT   1000000   // triples
#define NR   256       // relations
#define DQ   768       // question dim
#define DIN  1280      // DQ + 2*NR
#define NEB  (NE * NB) // 6.4M floats
#define NJ   257       // 256 W_inf rows + 1 W_att row
#define NW   (NE / 32) // 6250 mask words per hop

// ---- device scratch (static; no allocation) ----
__device__ float g_x0T[NEB];           // transposed seed x: [e][b]
__device__ float g_xh[3 * NEB];        // hop outputs, entity-major
__device__ float g_hqT[DQ * NB];       // transposed h_q: [d][b]
__device__ float g_rT[3 * NR * NB];    // r per hop: [j][b]
__device__ float g_c[3 * NB];          // attention logits per hop
__device__ unsigned g_mask[4 * NW];    // active-entity bitmask per hop input

// ---- transpose x (B x NE) -> (NE x B) and build hop-0 activity mask ----
__global__ void k_transpose_x(const float* __restrict__ src) {
    __shared__ float s[32][33];
    __shared__ unsigned smask;
    int lane = threadIdx.x, ty = threadIdx.y;
    if (ty == 0 && lane == 0) smask = 0;
    int cbase = blockIdx.x * 32;
#pragma unroll
    for (int row = ty; row < 32; row += 8)              // row = b
        s[row][lane] = src[(size_t)row * NE + cbase + lane];
    __syncthreads();
    unsigned local = 0;
#pragma unroll
    for (int row = ty; row < 32; row += 8) {            // row = entity offset
        float v = s[lane][row];                         // lane = b
        g_x0T[(size_t)(cbase + row) * NB + lane] = v;
        unsigned b = __ballot_sync(0xffffffffu, v != 0.0f);
        if (lane == 0 && b) local |= 1u << row;
    }
    if (lane == 0 && local) atomicOr(&smask, local);
    __syncthreads();
    if (ty == 0 && lane == 0) g_mask[blockIdx.x] = smask;
}

// ---- transpose h_q (B x DQ) -> (DQ x B) ----
__global__ void k_transpose_hq(const float* __restrict__ src) {
    __shared__ float s[32][33];
    int lane = threadIdx.x, ty = threadIdx.y;
    int cbase = blockIdx.x * 32;
#pragma unroll
    for (int row = ty; row < 32; row += 8)
        s[row][lane] = src[(size_t)row * DQ + cbase + lane];
    __syncthreads();
#pragma unroll
    for (int row = ty; row < 32; row += 8)
        g_hqT[(cbase + row) * NB + lane] = s[lane][row];
}

// ---- zero hop0 gemm accumulators (r_0, c_0) ----
__global__ void k_zero_small() {
    int i = blockIdx.x * blockDim.x + threadIdx.x;
    if (i < NR * NB) g_rT[i] = 0.f;
    if (i < NB) g_c[i] = 0.f;
}

// ---- zero hop outputs + masks 1..3 ----
__global__ void k_zero_big() {
    int i = blockIdx.x * blockDim.x + threadIdx.x;
    const int nf4 = 3 * NEB / 4;
    if (i < nf4) {
        reinterpret_cast<float4*>(g_xh)[i] = make_float4(0.f, 0.f, 0.f, 0.f);
    } else {
        int j = i - nf4;
        if (j < 3 * NW) g_mask[NW + j] = 0u;
    }
}

// ---- r_0 / c_0 = h_q @ [W_inf; W_att][:, :768].T  (split-d, atomic accum)
__global__ void k_gemm_base(const float* __restrict__ W_inf,
                            const float* __restrict__ W_att) {
    int lane = threadIdx.x, ty = threadIdx.y;
    int j = blockIdx.x;
    const float* w = (j == 256) ? W_att : W_inf + (size_t)j * DIN;
    int d0 = blockIdx.y * 192 + ty * 24;
    float a0 = 0.f, a1 = 0.f, a2 = 0.f, a3 = 0.f;
#pragma unroll
    for (int d = d0; d < d0 + 24; d += 4) {
        a0 += g_hqT[(d + 0) * NB + lane] * w[d + 0];
        a1 += g_hqT[(d + 1) * NB + lane] * w[d + 1];
        a2 += g_hqT[(d + 2) * NB + lane] * w[d + 2];
        a3 += g_hqT[(d + 3) * NB + lane] * w[d + 3];
    }
    __shared__ float s[8][32];
    s[ty][lane] = (a0 + a1) + (a2 + a3);
    __syncthreads();
    if (ty == 0) {
        float t = 0.f;
#pragma unroll
        for (int k = 0; k < 8; k++) t += s[k][lane];
        if (j == 256) atomicAdd(&g_c[lane], t);
        else          atomicAdd(&g_rT[j * NB + lane], t);
    }
}

// ---- hop 1/2 increment: out = hop0_out + r_parts @ W[:, 768:768+hop*256].T
__global__ void k_gemm_hop(const float* __restrict__ W_inf,
                           const float* __restrict__ W_att, int hop) {
    int lane = threadIdx.x, ty = threadIdx.y;
    int j = blockIdx.x;
    const float* w = (j == 256) ? W_att : W_inf + (size_t)j * DIN;
    float acc = 0.f;
    {   // most recent relation r_{hop-1}, weights w[768 .. 1024)
        const float* r1 = g_rT + (hop - 1) * NR * NB;
        const float* wd = w + DQ;
        int k0 = ty * 32;
#pragma unroll 8
        for (int k = k0; k < k0 + 32; k++)
            acc += r1[k * NB + lane] * wd[k];
    }
    if (hop == 2) {   // r_0, weights w[1024 .. 1280)
        const float* r2 = g_rT;
        const float* wd = w + DQ + NR;
        int k0 = ty * 32;
#pragma unroll 8
        for (int k = k0; k < k0 + 32; k++)
            acc += r2[k * NB + lane] * wd[k];
    }
    __shared__ float s[8][32];
    s[ty][lane] = acc;
    __syncthreads();
    if (ty == 0) {
        float t = (j == 256) ? g_c[lane] : g_rT[j * NB + lane];  // hop-0 base
#pragma unroll
        for (int k = 0; k < 8; k++) t += s[k][lane];
        if (j == 256) g_c[hop * NB + lane] = t;
        else          g_rT[hop * NR * NB + j * NB + lane] = t;
    }
}

// ---- masked gather * relation -> vector scatter-add.
// Warp holds 32 triples; active ones processed 4-at-a-time, 8 lanes per
// triple, float4 per lane, one red.global.add.v4.f32 per nonzero quad. ----
__global__ void k_scatter(const int* __restrict__ subj,
                          const int* __restrict__ rel,
                          const int* __restrict__ obj, int hop) {
    const float* __restrict__ rT = g_rT + hop * NR * NB;
    const float* __restrict__ xin = (hop == 0) ? g_x0T : (g_xh + (hop - 1) * NEB);
    float* xout = g_xh + hop * NEB;
    const unsigned* __restrict__ min_ = g_mask + hop * NW;
    unsigned* mout = g_mask + (hop + 1) * NW;

    int lane = threadIdx.x & 31;
    int sub = lane >> 3, quad = lane & 7;
    int t = blockIdx.x * blockDim.x + threadIdx.x;

    int s_i = 0, r_i = 0, o_i = 0;
    bool act = false;
    if (t < NT) {
        s_i = subj[t];
        act = (min_[s_i >> 5] >> (s_i & 31)) & 1u;
        if (act) { r_i = rel[t]; o_i = obj[t]; }
    }
    unsigned bal = __ballot_sync(0xffffffffu, act);
    while (bal) {
        unsigned b = bal;
        int i0 = __ffs(b) - 1; b &= b - 1;
        int i1 = __ffs(b) - 1; b &= b - 1;
        int i2 = __ffs(b) - 1; b &= b - 1;
        int i3 = __ffs(b) - 1; b &= b - 1;
        bal = b;
        int myi = (sub == 0) ? i0 : (sub == 1) ? i1 : (sub == 2) ? i2 : i3;
        bool on = (myi >= 0);
        int src = on ? myi : 0;
        int s = __shfl_sync(0xffffffffu, s_i, src);
        int r = __shfl_sync(0xffffffffu, r_i, src);
        int o = __shfl_sync(0xffffffffu, o_i, src);
        float4 p = make_float4(0.f, 0.f, 0.f, 0.f);
        bool nz = false;
        if (on) {
            float4 xv = *reinterpret_cast<const float4*>(&xin[(size_t)s * NB + quad * 4]);
            float4 rv = *reinterpret_cast<const float4*>(&rT[r * NB + quad * 4]);
            p.x = xv.x * rv.x; p.y = xv.y * rv.y;
            p.z = xv.z * rv.z; p.w = xv.w * rv.w;
            nz = (p.x != 0.f) | (p.y != 0.f) | (p.z != 0.f) | (p.w != 0.f);
        }
        unsigned nzb = __ballot_sync(0xffffffffu, nz);
        if (nz) {
            float* dst = &xout[(size_t)o * NB + quad * 4];
            asm volatile("red.global.add.v4.f32 [%0], {%1,%2,%3,%4};"
                         :: "l"(dst), "f"(p.x), "f"(p.y), "f"(p.z), "f"(p.w)
                         : "memory");
        }
        if (on && quad == 0 && ((nzb >> (sub * 8)) & 0xffu))
            atomicOr(&mout[o >> 5], 1u << (o & 31));
    }
}

// ---- softmax + masked weighted combine, transpose back to (B,NE) ----
__global__ void k_combine(float* __restrict__ out) {
    __shared__ float s[32][33];
    int lane = threadIdx.x, ty = threadIdx.y;
    float c0 = g_c[lane], c1 = g_c[NB + lane], c2 = g_c[2 * NB + lane];
    float m = fmaxf(c0, fmaxf(c1, c2));
    float e0 = expf(c0 - m), e1 = expf(c1 - m), e2 = expf(c2 - m);
    float inv = 1.0f / (e0 + e1 + e2);
    float a0 = e0 * inv, a1 = e1 * inv, a2 = e2 * inv;

    int bx = blockIdx.x;
    unsigned m1 = g_mask[NW + bx], m2 = g_mask[2 * NW + bx], m3 = g_mask[3 * NW + bx];
    int ebase = bx * 32;
#pragma unroll
    for (int row = ty; row < 32; row += 8) {           // row = e offset, lane = b
        int idx = (ebase + row) * NB + lane;
        float v = 0.f;
        if ((m1 >> row) & 1u) v += a0 * g_xh[idx];
        if ((m2 >> row) & 1u) v += a1 * g_xh[NEB + idx];
        if ((m3 >> row) & 1u) v += a2 * g_xh[2 * NEB + idx];
        s[row][lane] = v;
    }
    __syncthreads();
#pragma unroll
    for (int row = ty; row < 32; row += 8)             // row = b, lane = e offset
        out[(size_t)row * NE + ebase + lane] = s[lane][row];
}

extern "C" void kernel_launch(void* const* d_in, const int* in_sizes, int n_in,
                              void* d_out, int out_size) {
    const float* x     = (const float*)d_in[0];
    const float* h_q   = (const float*)d_in[1];
    const float* W_inf = (const float*)d_in[2];
    const float* W_att = (const float*)d_in[3];
    const int*   subj  = (const int*)d_in[4];
    const int*   rel   = (const int*)d_in[5];
    const int*   obj   = (const int*)d_in[6];
    float* out = (float*)d_out;

    static cudaStream_t s1 = nullptr, s2 = nullptr;
    static cudaEvent_t eF = nullptr, e1 = nullptr, eB = nullptr,
                       eH1 = nullptr, eH2 = nullptr;
    if (!s1) {
        cudaStreamCreateWithFlags(&s1, cudaStreamNonBlocking);
        cudaStreamCreateWithFlags(&s2, cudaStreamNonBlocking);
        cudaEventCreateWithFlags(&eF,  cudaEventDisableTiming);
        cudaEventCreateWithFlags(&e1,  cudaEventDisableTiming);
        cudaEventCreateWithFlags(&eB,  cudaEventDisableTiming);
        cudaEventCreateWithFlags(&eH1, cudaEventDisableTiming);
        cudaEventCreateWithFlags(&eH2, cudaEventDisableTiming);
    }

    dim3 tb(32, 8);
    // fork side stream: x transpose + big zero
    cudaEventRecord(eF, 0);
    cudaStreamWaitEvent(s1, eF, 0);
    k_transpose_x<<<NE / 32, tb, 0, s1>>>(x);
    {
        int zthreads = 3 * NEB / 4 + 3 * NW;
        k_zero_big<<<(zthreads + 255) / 256, 256, 0, s1>>>();
    }
    cudaEventRecord(e1, s1);

    // main stream: gemm chain prerequisites
    k_zero_small<<<(NR * NB + 255) / 256, 256>>>();
    k_transpose_hq<<<DQ / 32, tb>>>(h_q);
    k_gemm_base<<<dim3(NJ, 4), tb>>>(W_inf, W_att);
    cudaEventRecord(eB, 0);
    // fork gemm hops (independent of scatters)
    cudaStreamWaitEvent(s2, eB, 0);
    k_gemm_hop<<<NJ, tb, 0, s2>>>(W_inf, W_att, 1);
    cudaEventRecord(eH1, s2);
    k_gemm_hop<<<NJ, tb, 0, s2>>>(W_inf, W_att, 2);
    cudaEventRecord(eH2, s2);

    int sblocks = (NT + 255) / 256;
    cudaStreamWaitEvent(0, e1, 0);
    k_scatter<<<sblocks, 256>>>(subj, rel, obj, 0);
    cudaStreamWaitEvent(0, eH1, 0);
    k_scatter<<<sblocks, 256>>>(subj, rel, obj, 1);
    cudaStreamWaitEvent(0, eH2, 0);
    k_scatter<<<sblocks, 256>>>(subj, rel, obj, 2);
    k_combine<<<NE / 32, tb>>>(out);
}